// round 15
// baseline (speedup 1.0000x reference)
#include <cuda_runtime.h>
#include <cuda_bf16.h>
#include <cstdint>
#include <cstddef>

#define L_SEQ 2048
#define DM    1024
#define NH    16
#define HD    64
#define RSCALE 0.125f
typedef __nv_bfloat16 bf16;
typedef __nv_bfloat162 bf162;
typedef unsigned int u32;

// ---------------- scratch ----------------
__device__ bf16 g_xh[L_SEQ*DM],  g_xl[L_SEQ*DM];
__device__ bf16 g_sh[L_SEQ*DM],  g_sl[L_SEQ*DM];
__device__ bf16 g_wqah[DM*DM], g_wqal[DM*DM];
__device__ bf16 g_wqrh[DM*DM], g_wqrl[DM*DM];
__device__ bf16 g_woh [DM*DM], g_wol [DM*DM];
__device__ bf16 g_wkah[HD*DM], g_wkal[HD*DM];
__device__ bf16 g_wkrh[HD*DM], g_wkrl[HD*DM];
__device__ bf16 g_wvh [HD*DM], g_wvl [HD*DM];
__device__ bf16 g_qah[NH*L_SEQ*HD], g_qal[NH*L_SEQ*HD];
__device__ bf16 g_qrh[NH*L_SEQ*HD], g_qrl[NH*L_SEQ*HD];
__device__ bf16 g_kah[L_SEQ*HD], g_kal[L_SEQ*HD];
__device__ bf16 g_krh[L_SEQ*HD], g_krl[L_SEQ*HD];
__device__ bf16 g_vth[HD*L_SEQ], g_vtl[HD*L_SEQ];
__device__ bf16 g_aoh[L_SEQ*DM], g_aol[L_SEQ*DM];

// ---------------- helpers ----------------
__device__ __forceinline__ void split2(float v, bf16& hi, bf16& lo) {
    hi = __float2bfloat16(v);
    lo = __float2bfloat16(v - __bfloat162float(hi));
}
__device__ __forceinline__ void packsplit(float a, float b, u32& ph, u32& pl) {
    float ah = __bfloat162float(__float2bfloat16(a));
    float bh = __bfloat162float(__float2bfloat16(b));
    bf162 hv = __floats2bfloat162_rn(ah, bh);
    bf162 lv = __floats2bfloat162_rn(a - ah, b - bh);
    ph = *reinterpret_cast<u32*>(&hv);
    pl = *reinterpret_cast<u32*>(&lv);
}
__device__ __forceinline__ void ldsm4(u32 addr, u32& r0, u32& r1, u32& r2, u32& r3) {
    asm volatile("ldmatrix.sync.aligned.m8n8.x4.shared.b16 {%0,%1,%2,%3}, [%4];"
                 : "=r"(r0), "=r"(r1), "=r"(r2), "=r"(r3) : "r"(addr));
}
__device__ __forceinline__ void hmma(float* c, u32 a0, u32 a1, u32 a2, u32 a3,
                                     u32 b0, u32 b1) {
    asm volatile("mma.sync.aligned.m16n8k16.row.col.f32.bf16.bf16.f32 "
                 "{%0,%1,%2,%3},{%4,%5,%6,%7},{%8,%9},{%0,%1,%2,%3};"
                 : "+f"(c[0]), "+f"(c[1]), "+f"(c[2]), "+f"(c[3])
                 : "r"(a0), "r"(a1), "r"(a2), "r"(a3), "r"(b0), "r"(b1));
}
__device__ __forceinline__ u32 addrA(u32 base, int ldb, int m0, int k0, int lane) {
    int g = lane & 7, grp = lane >> 3;
    return base + (u32)((m0 + g + (grp & 1) * 8) * ldb + (k0 + (grp >> 1) * 8) * 2);
}
__device__ __forceinline__ u32 addrB(u32 base, int ldb, int n0, int k0, int lane) {
    int g = lane & 7, grp = lane >> 3;
    return base + (u32)((n0 + g + (grp >> 1) * 8) * ldb + (k0 + (grp & 1) * 8) * 2);
}
__device__ __forceinline__ void cpasync16(u32 dst, const void* src) {
    asm volatile("cp.async.cg.shared.global [%0], [%1], 16;" :: "r"(dst), "l"(src));
}
__device__ __forceinline__ void cpcommit() { asm volatile("cp.async.commit_group;"); }
__device__ __forceinline__ void cpwait0() { asm volatile("cp.async.wait_group 0;"); }
__device__ __forceinline__ void cpwait1() { asm volatile("cp.async.wait_group 1;"); }
__device__ __forceinline__ void st_bf2(bf16* base, size_t off, float a, float b) {
    *reinterpret_cast<bf162*>(base + off) = __floats2bfloat162_rn(a, b);
}

// ---------------- input split ----------------
__global__ void split_in(const float* __restrict__ x, const float* __restrict__ s) {
    int i = blockIdx.x * 256 + threadIdx.x;
    if (i < L_SEQ * DM) {
        split2(x[i], g_xh[i], g_xl[i]);
    } else {
        int k = i - L_SEQ * DM;
        if (k < L_SEQ * DM) split2(s[k], g_sh[k], g_sl[k]);
    }
}

// ---------------- zero the non-causal attn region ----------------
__global__ __launch_bounds__(256) void zero_upper(float* __restrict__ attn) {
    const int i = blockIdx.x, hq = blockIdx.y;
    const int W = (((i >> 6) + 1) << 6);
    if (W >= L_SEQ) return;
    float* row = attn + ((size_t)hq * L_SEQ + i) * L_SEQ;
    float4 z = make_float4(0.f, 0.f, 0.f, 0.f);
    for (int c = W + threadIdx.x * 4; c < L_SEQ; c += 256 * 4)
        *(float4*)&row[c] = z;
}

// ---------------- weight transpose + split ----------------
__global__ void tsplit_big(const float* __restrict__ w0, const float* __restrict__ w1,
                           const float* __restrict__ w2) {
    __shared__ float t[32][33];
    int z = blockIdx.z;
    const float* src = (z == 0) ? w0 : (z == 1) ? w1 : w2;
    bf16* dh = (z == 0) ? g_wqah : (z == 1) ? g_wqrh : g_woh;
    bf16* dl = (z == 0) ? g_wqal : (z == 1) ? g_wqrl : g_wol;
    int k0 = blockIdx.x * 32, n0 = blockIdx.y * 32;
    int tx = threadIdx.x & 31, ty0 = threadIdx.x >> 5;
#pragma unroll
    for (int q = 0; q < 4; ++q) {
        int ty = ty0 * 4 + q;
        t[ty][tx] = src[(size_t)(k0 + ty) * DM + n0 + tx];
    }
    __syncthreads();
#pragma unroll
    for (int q = 0; q < 4; ++q) {
        int ty = ty0 * 4 + q;
        bf16 hh, ll; split2(t[tx][ty], hh, ll);
        size_t o = (size_t)(n0 + ty) * DM + k0 + tx;
        dh[o] = hh; dl[o] = ll;
    }
}
__global__ void tsplit_small(const float* __restrict__ w0, const float* __restrict__ w1,
                             const float* __restrict__ w2) {
    __shared__ float t[32][33];
    int z = blockIdx.z;
    const float* src = (z == 0) ? w0 : (z == 1) ? w1 : w2;
    bf16* dh = (z == 0) ? g_wkah : (z == 1) ? g_wkrh : g_wvh;
    bf16* dl = (z == 0) ? g_wkal : (z == 1) ? g_wkrl : g_wvl;
    int k0 = blockIdx.x * 32, n0 = blockIdx.y * 32;
    int tx = threadIdx.x & 31, ty0 = threadIdx.x >> 5;
#pragma unroll
    for (int q = 0; q < 4; ++q) {
        int ty = ty0 * 4 + q;
        t[ty][tx] = src[(size_t)(k0 + ty) * HD + n0 + tx];
    }
    __syncthreads();
#pragma unroll
    for (int q = 0; q < 4; ++q) {
        int ty = ty0 * 4 + q;
        bf16 hh, ll; split2(t[tx][ty], hh, ll);
        size_t o = (size_t)(n0 + ty) * DM + k0 + tx;
        dh[o] = hh; dl[o] = ll;
    }
}

// ---------------- big GEMM: BM=128 BN=64 BK=32, 3-stage, 2 CTA/SM ----------------
template <int MODE>
__global__ __launch_bounds__(256, 2) void gemm_big(
    const bf16* __restrict__ Ah,  const bf16* __restrict__ Al,
    const bf16* __restrict__ Bh0, const bf16* __restrict__ Bl0, float* __restrict__ C0,
    const bf16* __restrict__ Bh1, const bf16* __restrict__ Bl1, float* __restrict__ C1,
    const float* __restrict__ fcos, const float* __restrict__ fsin, int m_off) {
    extern __shared__ bf16 dsm[];
    const bf16* Bh = blockIdx.z ? Bh1 : Bh0;
    const bf16* Bl = blockIdx.z ? Bl1 : Bl0;
    float* C = blockIdx.z ? C1 : C0;
    const int tid = threadIdx.x, lane = tid & 31, warp = tid >> 5;
    const int wm = warp & 3, wn = warp >> 2;
    const int m0 = m_off + blockIdx.y * 128, n0 = blockIdx.x * 64;
    u32 ub = (u32)__cvta_generic_to_shared(dsm);

    float acc[2][4][4];
#pragma unroll
    for (int m2 = 0; m2 < 2; ++m2)
#pragma unroll
        for (int o = 0; o < 4; ++o)
#pragma unroll
            for (int k = 0; k < 4; ++k) acc[m2][o][k] = 0.f;

    auto issue = [&](int k0, int st) {
        u32 base = ub + (u32)st * 30720u;
#pragma unroll
        for (int it = 0; it < 4; ++it) {
            int idx = it * 256 + tid;
            int pl = idx >> 9, rem = idx & 511, r = rem >> 2, s = rem & 3;
            const bf16* src = pl ? Al : Ah;
            cpasync16(base + (u32)pl * 10240u + r * 80 + s * 16,
                      src + (size_t)(m0 + r) * DM + k0 + s * 8);
        }
#pragma unroll
        for (int it = 0; it < 2; ++it) {
            int idx = it * 256 + tid;
            int pl = idx >> 8, rem = idx & 255, r = rem >> 2, s = rem & 3;
            const bf16* src = pl ? Bl : Bh;
            cpasync16(base + 20480u + (u32)pl * 5120u + r * 80 + s * 16,
                      src + (size_t)(n0 + r) * DM + k0 + s * 8);
        }
        cpcommit();
    };

    const int NK = DM / 32;
    issue(0, 0);
    issue(32, 1);
    for (int kt = 0; kt < NK; ++kt) {
        if (kt == NK - 1) cpwait0(); else cpwait1();
        __syncthreads();
        if (kt + 2 < NK) issue((kt + 2) * 32, (kt + 2) % 3);
        u32 base = ub + (u32)(kt % 3) * 30720u;
        u32 aH = base, aL = base + 10240u, bH = base + 20480u, bL = base + 25600u;
#pragma unroll
        for (int ks = 0; ks < 2; ++ks) {
            int kk = ks * 16;
            u32 ah[2][4], al[2][4], bh[2][4], bl[2][4];
#pragma unroll
            for (int m2 = 0; m2 < 2; ++m2) {
                ldsm4(addrA(aH, 80, wm * 32 + m2 * 16, kk, lane),
                      ah[m2][0], ah[m2][1], ah[m2][2], ah[m2][3]);
                ldsm4(addrA(aL, 80, wm * 32 + m2 * 16, kk, lane),
                      al[m2][0], al[m2][1], al[m2][2], al[m2][3]);
            }
#pragma unroll
            for (int q = 0; q < 2; ++q) {
                ldsm4(addrB(bH, 80, wn * 32 + q * 16, kk, lane),
                      bh[q][0], bh[q][1], bh[q][2], bh[q][3]);
                ldsm4(addrB(bL, 80, wn * 32 + q * 16, kk, lane),
                      bl[q][0], bl[q][1], bl[q][2], bl[q][3]);
            }
#pragma unroll
            for (int m2 = 0; m2 < 2; ++m2)
#pragma unroll
                for (int o = 0; o < 4; ++o) {
                    int q = o >> 1, pp = (o & 1) * 2;
                    hmma(acc[m2][o], ah[m2][0], ah[m2][1], ah[m2][2], ah[m2][3],
                         bh[q][pp], bh[q][pp + 1]);
                    hmma(acc[m2][o], ah[m2][0], ah[m2][1], ah[m2][2], ah[m2][3],
                         bl[q][pp], bl[q][pp + 1]);
                    hmma(acc[m2][o], al[m2][0], al[m2][1], al[m2][2], al[m2][3],
                         bh[q][pp], bh[q][pp + 1]);
                }
        }
    }
    const int g = lane >> 2, t = lane & 3;
    if (MODE == 0) {
#pragma unroll
        for (int m2 = 0; m2 < 2; ++m2)
#pragma unroll
            for (int o = 0; o < 4; ++o) {
                int row = m0 + wm * 32 + m2 * 16 + g;
                int col = n0 + wn * 32 + o * 8 + 2 * t;
                *(float2*)&C[(size_t)row * DM + col] = make_float2(acc[m2][o][0], acc[m2][o][1]);
                *(float2*)&C[(size_t)(row + 8) * DM + col] = make_float2(acc[m2][o][2], acc[m2][o][3]);
            }
    } else {
        bf16* dh = blockIdx.z ? g_qrh : g_qah;
        bf16* dl = blockIdx.z ? g_qrl : g_qal;
        const bool doRope = (blockIdx.z == 0);
#pragma unroll
        for (int m2 = 0; m2 < 2; ++m2)
#pragma unroll
            for (int o = 0; o < 4; ++o) {
                int col = n0 + wn * 32 + o * 8 + 2 * t;
                int hq = col >> 6, d = col & 63, pidx = d >> 1;
#pragma unroll
                for (int half = 0; half < 2; ++half) {
                    int row = m0 + wm * 32 + m2 * 16 + g + half * 8;
                    float v0 = acc[m2][o][half * 2], v1 = acc[m2][o][half * 2 + 1];
                    float o0, o1;
                    if (doRope) {
                        float cc = fcos[row * 32 + pidx], ss = fsin[row * 32 + pidx];
                        o0 = (v0 * cc - v1 * ss) * RSCALE;
                        o1 = (v0 * ss + v1 * cc) * RSCALE;
                    } else {
                        o0 = v0 * RSCALE; o1 = v1 * RSCALE;
                    }
                    bf16 h0, l0, h1, l1;
                    split2(o0, h0, l0); split2(o1, h1, l1);
                    size_t off = ((size_t)hq * L_SEQ + row) * HD + d;
                    st_bf2(dh, off, __bfloat162float(h0), __bfloat162float(h1));
                    st_bf2(dl, off, __bfloat162float(l0), __bfloat162float(l1));
                }
            }
    }
}

// ---------------- 3 small projections + rope/split/transpose epilogue ---------
__global__ __launch_bounds__(256, 2) void proj3(const float* __restrict__ fcos,
                                                const float* __restrict__ fsin) {
    __shared__ bf16 sA[2 * 2 * 64 * 40];
    __shared__ bf16 sB[2 * 2 * 64 * 40];
    const int z = blockIdx.y;
    const bf16* Ah = (z == 2) ? g_sh : g_xh;
    const bf16* Al = (z == 2) ? g_sl : g_xl;
    const bf16* Bh = (z == 0) ? g_wkah : (z == 1) ? g_wkrh : g_wvh;
    const bf16* Bl = (z == 0) ? g_wkal : (z == 1) ? g_wkrl : g_wvl;

    const int tid = threadIdx.x, lane = tid & 31, warp = tid >> 5;
    const int wm = warp & 3, wn = warp >> 2;
    const int m0 = blockIdx.x * 64;
    u32 ua = (u32)__cvta_generic_to_shared(sA);
    u32 ub = (u32)__cvta_generic_to_shared(sB);

    float acc[4][4];
#pragma unroll
    for (int o = 0; o < 4; ++o)
#pragma unroll
        for (int k = 0; k < 4; ++k) acc[o][k] = 0.f;

    auto issue = [&](int k0, int st) {
#pragma unroll
        for (int it = 0; it < 2; ++it) {
            int idx = it * 256 + tid;
            int pl = idx >> 8, rem = idx & 255, r = rem >> 2, s = rem & 3;
            const bf16* src = pl ? Al : Ah;
            cpasync16(ua + (u32)(st * 2 + pl) * 5120u + r * 80 + s * 16,
                      src + (size_t)(m0 + r) * DM + k0 + s * 8);
        }
#pragma unroll
        for (int it = 0; it < 2; ++it) {
            int idx = it * 256 + tid;
            int pl = idx >> 8, rem = idx & 255, r = rem >> 2, s = rem & 3;
            const bf16* src = pl ? Bl : Bh;
            cpasync16(ub + (u32)(st * 2 + pl) * 5120u + r * 80 + s * 16,
                      src + (size_t)r * DM + k0 + s * 8);
        }
        cpcommit();
    };

    issue(0, 0);
    const int NK = DM / 32;
    for (int kt = 0; kt < NK; ++kt) {
        if (kt + 1 < NK) { issue((kt + 1) * 32, (kt + 1) & 1); cpwait1(); }
        else cpwait0();
        __syncthreads();
        int st = kt & 1;
        u32 aH = ua + (u32)(st * 2) * 5120u, aL = aH + 5120u;
        u32 bH = ub + (u32)(st * 2) * 5120u, bL = bH + 5120u;
#pragma unroll
        for (int ks = 0; ks < 2; ++ks) {
            int kk = ks * 16;
            u32 ah[4], al[4], bh[2][4], bl[2][4];
            ldsm4(addrA(aH, 80, wm * 16, kk, lane), ah[0], ah[1], ah[2], ah[3]);
            ldsm4(addrA(aL, 80, wm * 16, kk, lane), al[0], al[1], al[2], al[3]);
#pragma unroll
            for (int q = 0; q < 2; ++q) {
                ldsm4(addrB(bH, 80, wn * 32 + q * 16, kk, lane),
                      bh[q][0], bh[q][1], bh[q][2], bh[q][3]);
                ldsm4(addrB(bL, 80, wn * 32 + q * 16, kk, lane),
                      bl[q][0], bl[q][1], bl[q][2], bl[q][3]);
            }
#pragma unroll
            for (int o = 0; o < 4; ++o) {
                int q = o >> 1, pp = (o & 1) * 2;
                hmma(acc[o], ah[0], ah[1], ah[2], ah[3], bh[q][pp], bh[q][pp + 1]);
                hmma(acc[o], ah[0], ah[1], ah[2], ah[3], bl[q][pp], bl[q][pp + 1]);
                hmma(acc[o], al[0], al[1], al[2], al[3], bh[q][pp], bh[q][pp + 1]);
            }
        }
        __syncthreads();
    }
    const int g = lane >> 2, t = lane & 3;
#pragma unroll
    for (int o = 0; o < 4; ++o) {
        int col = wn * 32 + o * 8 + 2 * t;
#pragma unroll
        for (int half = 0; half < 2; ++half) {
            int row = m0 + wm * 16 + g + half * 8;
            float v0 = acc[o][half * 2], v1 = acc[o][half * 2 + 1];
            if (z == 0) {
                int pidx = col >> 1;
                float cc = fcos[row * 32 + pidx], ss = fsin[row * 32 + pidx];
                float o0 = v0 * cc - v1 * ss, o1 = v0 * ss + v1 * cc;
                bf16 h0, l0, h1, l1;
                split2(o0, h0, l0); split2(o1, h1, l1);
                size_t off = (size_t)row * HD + col;
                st_bf2(g_kah, off, __bfloat162float(h0), __bfloat162float(h1));
                st_bf2(g_kal, off, __bfloat162float(l0), __bfloat162float(l1));
            } else if (z == 1) {
                bf16 h0, l0, h1, l1;
                split2(v0, h0, l0); split2(v1, h1, l1);
                size_t off = (size_t)row * HD + col;
                st_bf2(g_krh, off, __bfloat162float(h0), __bfloat162float(h1));
                st_bf2(g_krl, off, __bfloat162float(l0), __bfloat162float(l1));
            } else {
                bf16 h0, l0, h1, l1;
                split2(v0, h0, l0); split2(v1, h1, l1);
                g_vth[(size_t)col * L_SEQ + row] = h0;
                g_vtl[(size_t)col * L_SEQ + row] = l0;
                g_vth[(size_t)(col + 1) * L_SEQ + row] = h1;
                g_vtl[(size_t)(col + 1) * L_SEQ + row] = l1;
            }
        }
    }
}

// ---------------- attention: BM=64, 256 thr ----------------
__device__ __forceinline__ void mma_qk16(u32 aH, u32 aL, u32 bH, u32 bL,
                                         int wm, int wn, int lane, float cs[4][4]) {
#pragma unroll
    for (int ks = 0; ks < 4; ++ks) {
        int k0 = ks * 16;
        u32 ah[4], al[4], bh[2][4], bl[2][4];
        ldsm4(addrA(aH, 144, wm * 16, k0, lane), ah[0], ah[1], ah[2], ah[3]);
        ldsm4(addrA(aL, 144, wm * 16, k0, lane), al[0], al[1], al[2], al[3]);
#pragma unroll
        for (int q = 0; q < 2; ++q) {
            ldsm4(addrB(bH, 144, wn * 32 + q * 16, k0, lane),
                  bh[q][0], bh[q][1], bh[q][2], bh[q][3]);
            ldsm4(addrB(bL, 144, wn * 32 + q * 16, k0, lane),
                  bl[q][0], bl[q][1], bl[q][2], bl[q][3]);
        }
#pragma unroll
        for (int o = 0; o < 4; ++o) {
            int q = o >> 1, pp = (o & 1) * 2;
            hmma(cs[o], ah[0], ah[1], ah[2], ah[3], bh[q][pp], bh[q][pp + 1]);
            hmma(cs[o], ah[0], ah[1], ah[2], ah[3], bl[q][pp], bl[q][pp + 1]);
            hmma(cs[o], al[0], al[1], al[2], al[3], bh[q][pp], bh[q][pp + 1]);
        }
    }
}

__device__ __forceinline__ void store_frag16(float* dst, float c[4][4],
                                             int wm, int wn, int g, int t) {
#pragma unroll
    for (int o = 0; o < 4; ++o) {
        int row = wm * 16 + g;
        int col = wn * 32 + o * 8 + 2 * t;
        *(float2*)&dst[(size_t)row * L_SEQ + col] = make_float2(c[o][0], c[o][1]);
        *(float2*)&dst[(size_t)(row + 8) * L_SEQ + col] = make_float2(c[o][2], c[o][3]);
    }
}

#define ASM_RING 36864u
#define ASM_LS   147456u

__global__ __launch_bounds__(256, 1) void attn_mma(float* __restrict__ attn_out,
                                                   float* __restrict__ rel_out,
                                                   int ib_top) {
    extern __shared__ char smraw[];
    u32 usm = (u32)__cvta_generic_to_shared(smraw);
    float* lsum = (float*)(smraw + ASM_LS);
    float* linv = lsum + 128;
    float* osc  = (float*)(smraw + ASM_RING);

    const int hq = blockIdx.y;
    const int ib = ib_top - blockIdx.x;
    const int i0 = ib * 64;
    const int tid = threadIdx.x, lane = tid & 31, warp = tid >> 5;
    const int wm = warp >> 1, wn = warp & 1;
    const int g = lane >> 2, t = lane & 3;
    const int jtmax = ib;

    {
        const bf16* srcs[4] = {g_qah + ((size_t)hq * L_SEQ + i0) * HD,
                               g_qal + ((size_t)hq * L_SEQ + i0) * HD,
                               g_qrh + ((size_t)hq * L_SEQ + i0) * HD,
                               g_qrl + ((size_t)hq * L_SEQ + i0) * HD};
#pragma unroll
        for (int a = 0; a < 4; ++a)
#pragma unroll
            for (int it = 0; it < 2; ++it) {
                int idx = it * 256 + tid;
                int r = idx >> 3, s = idx & 7;
                *(uint4*)(smraw + a * 9216 + r * 144 + s * 16) =
                    *(const uint4*)&srcs[a][(size_t)r * HD + s * 8];
            }
    }
    const u32 uqa_h = usm, uqa_l = usm + 9216u;
    const u32 uqr_h = usm + 18432u, uqr_l = usm + 27648u;
    auto ring = [&](int st, int pl) -> u32 {
        return usm + ASM_RING + (u32)st * 55296u + (u32)pl * 9216u;
    };

    auto issue_tiles = [&](int jt, int st, bool causal) {
#pragma unroll
        for (int it = 0; it < 4; ++it) {
            int idx = it * 256 + tid;
            int pl = idx >> 9, rem = idx & 511, r = rem >> 3, s = rem & 7;
            const bf16* src = pl ? g_krl : g_krh;
            cpasync16(ring(st, 2 + pl) + r * 144 + s * 16,
                      src + (size_t)(jt * 64 + r) * HD + s * 8);
        }
        if (causal) {
#pragma unroll
            for (int it = 0; it < 4; ++it) {
                int idx = it * 256 + tid;
                int pl = idx >> 9, rem = idx & 511, r = rem >> 3, s = rem & 7;
                const bf16* src = pl ? g_kal : g_kah;
                cpasync16(ring(st, pl) + r * 144 + s * 16,
                          src + (size_t)(jt * 64 + r) * HD + s * 8);
            }
#pragma unroll
            for (int it = 0; it < 4; ++it) {
                int idx = it * 256 + tid;
                int pl = idx >> 9, rem = idx & 511, r = rem >> 3, s = rem & 7;
                const bf16* src = pl ? g_vtl : g_vth;
                cpasync16(ring(st, 4 + pl) + r * 144 + s * 16,
                          src + (size_t)r * L_SEQ + jt * 64 + s * 8);
            }
        }
        cpcommit();
    };

    float esum[2] = {0.f, 0.f};
    float co[8][4];
#pragma unroll
    for (int o = 0; o < 8; ++o)
#pragma unroll
        for (int k = 0; k < 4; ++k) co[o][k] = 0.f;

    float* attnp = attn_out + (size_t)hq * L_SEQ * L_SEQ + (size_t)i0 * L_SEQ;
    float* relp  = rel_out  + (size_t)hq * L_SEQ * L_SEQ + (size_t)i0 * L_SEQ;

    issue_tiles(0, 0, true);
    for (int jt = 0; jt < 32; ++jt) {
        const bool causal = (jt <= jtmax);
        cpwait0();
        __syncthreads();
        if (jt < 31) issue_tiles(jt + 1, (jt + 1) & 1, (jt + 1) <= jtmax);
        int st = jt & 1;

        float cr[4][4];
#pragma unroll
        for (int o = 0; o < 4; ++o)
#pragma unroll
            for (int k = 0; k < 4; ++k) cr[o][k] = 0.f;
        mma_qk16(uqr_h, uqr_l, ring(st, 2), ring(st, 3), wm, wn, lane, cr);
        store_frag16(relp + jt * 64, cr, wm, wn, g, t);

        if (!causal) continue;

        float csq[4][4];
#pragma unroll
        for (int o = 0; o < 4; ++o)
#pragma unroll
            for (int k = 0; k < 4; ++k) csq[o][k] = 0.f;
        mma_qk16(uqa_h, uqa_l, ring(st, 0), ring(st, 1), wm, wn, lane, csq);

        const bool dia = (jt == ib);
        const int r0 = i0 + wm * 16 + g;
#pragma unroll
        for (int o = 0; o < 4; ++o) {
            int cb = jt * 64 + wn * 32 + o * 8 + 2 * t;
            float p0 = __expf(csq[o][0]);
            float p1 = __expf(csq[o][1]);
            float p2 = __expf(csq[o][2]);
            float p3 = __expf(csq[o][3]);
            if (dia) {
                if (cb     > r0)     p0 = 0.f;
                if (cb + 1 > r0)     p1 = 0.f;
                if (cb     > r0 + 8) p2 = 0.f;
                if (cb + 1 > r0 + 8) p3 = 0.f;
            }
            esum[0] += p0 + p1;
            esum[1] += p2 + p3;
            csq[o][0] = p0; csq[o][1] = p1; csq[o][2] = p2; csq[o][3] = p3;
        }
        store_frag16(attnp + jt * 64, csq, wm, wn, g, t);

#pragma unroll
        for (int b = 0; b < 2; ++b) {
            float pr[8];
#pragma unroll
            for (int k = 0; k < 4; ++k) {
                pr[k]     = csq[2 * b][k]     * cr[2 * b][k];
                pr[4 + k] = csq[2 * b + 1][k] * cr[2 * b + 1][k];
            }
            u32 aH[4], aL[4];
            packsplit(pr[0], pr[1], aH[0], aL[0]);
            packsplit(pr[2], pr[3], aH[1], aL[1]);
            packsplit(pr[4], pr[5], aH[2], aL[2]);
            packsplit(pr[6], pr[7], aH[3], aL[3]);
#pragma unroll
            for (int q2 = 0; q2 < 4; ++q2) {
                u32 vh[4], vl[4];
                ldsm4(addrB(ring(st, 4), 144, q2 * 16, wn * 32 + b * 16, lane),
                      vh[0], vh[1], vh[2], vh[3]);
                ldsm4(addrB(ring(st, 5), 144, q2 * 16, wn * 32 + b * 16, lane),
                      vl[0], vl[1], vl[2], vl[3]);
#pragma unroll
                for (int sub = 0; sub < 2; ++sub) {
                    int o = q2 * 2 + sub, pp = sub * 2;
                    hmma(co[o], aH[0], aH[1], aH[2], aH[3], vh[pp], vh[pp + 1]);
                    hmma(co[o], aH[0], aH[1], aH[2], aH[3], vl[pp], vl[pp + 1]);
                    hmma(co[o], aL[0], aL[1], aL[2], aL[3], vh[pp], vh[pp + 1]);
                }
            }
        }
    }

#pragma unroll
    for (int hf = 0; hf < 2; ++hf) {
        float v = esum[hf];
        v += __shfl_xor_sync(0xffffffffu, v, 1);
        v += __shfl_xor_sync(0xffffffffu, v, 2);
        esum[hf] = v;
    }
    __syncthreads();
    if (t == 0) {
        lsum[wn * 64 + wm * 16 + g] = esum[0];
        lsum[wn * 64 + wm * 16 + g + 8] = esum[1];
    }
    __syncthreads();
    if (tid < 64) linv[tid] = __fdividef(1.f, lsum[tid] + lsum[64 + tid]);
    __syncthreads();

    if (wn == 0) {
#pragma unroll
        for (int o = 0; o < 8; ++o) {
            int row = wm * 16 + g;
            int col = o * 8 + 2 * t;
            *(float2*)&osc[row * 68 + col] = make_float2(co[o][0], co[o][1]);
            *(float2*)&osc[(row + 8) * 68 + col] = make_float2(co[o][2], co[o][3]);
        }
    }
    __syncthreads();
    if (wn == 1) {
#pragma unroll
        for (int o = 0; o < 8; ++o) {
            int row = wm * 16 + g;
            int col = o * 8 + 2 * t;
            osc[row * 68 + col]           += co[o][0];
            osc[row * 68 + col + 1]       += co[o][1];
            osc[(row + 8) * 68 + col]     += co[o][2];
            osc[(row + 8) * 68 + col + 1] += co[o][3];
        }
    }
    __syncthreads();
#pragma unroll
    for (int it = 0; it < 16; ++it) {
        int idx = it * 256 + tid;
        int r = idx >> 6, d = idx & 63;
        float v = osc[r * 68 + d] * linv[r];
        bf16 hh, ll; split2(v, hh, ll);
        size_t off = (size_t)(i0 + r) * DM + hq * 64 + d;
        g_aoh[off] = hh; g_aol[off] = ll;
    }

    {
        int r = tid >> 2;
        float sc = linv[r];
        int Wr = (ib + 1) << 6;
        float* row = attnp + (size_t)r * L_SEQ;
        for (int c = (tid & 3) * 4; c < Wr; c += 16) {
            float4 v = *(float4*)&row[c];
            v.x *= sc; v.y *= sc; v.z *= sc; v.w *= sc;
            *(float4*)&row[c] = v;
        }
    }
}

// ---------------------------------- launch ----------------------------------
extern "C" void kernel_launch(void* const* d_in, const int* in_sizes, int n_in,
                              void* d_out, int out_size) {
    (void)in_sizes; (void)n_in; (void)out_size;
    const float* x    = (const float*)d_in[0];
    const float* sym  = (const float*)d_in[1];
    const float* fcos = (const float*)d_in[2];
    const float* fsin = (const float*)d_in[3];
    const float* wqa  = (const float*)d_in[4];
    const float* wka  = (const float*)d_in[5];
    const float* wqr  = (const float*)d_in[6];
    const float* wkr  = (const float*)d_in[7];
    const float* wv   = (const float*)d_in[8];
    const float* wo   = (const float*)d_in[9];

    float* out  = (float*)d_out;
    float* attn = out + (size_t)L_SEQ * DM;
    float* rel  = attn + (size_t)NH * L_SEQ * L_SEQ;

    void* p;
#define GS(var, sym_) cudaGetSymbolAddress(&p, sym_); bf16* var = (bf16*)p;
    GS(xh, g_xh)   GS(xl, g_xl)
    GS(wqah, g_wqah) GS(wqal, g_wqal) GS(wqrh, g_wqrh) GS(wqrl, g_wqrl)
    GS(woh, g_woh)   GS(wol, g_wol)
    GS(aoh, g_aoh)   GS(aol, g_aol)
#undef GS

    static cudaStream_t s2 = nullptr;
    static cudaEvent_t ev0 = nullptr, ev1 = nullptr, evH = nullptr, evU = nullptr;
    if (!s2) {
        cudaStreamCreateWithFlags(&s2, cudaStreamNonBlocking);
        cudaEventCreateWithFlags(&ev0, cudaEventDisableTiming);
        cudaEventCreateWithFlags(&ev1, cudaEventDisableTiming);
        cudaEventCreateWithFlags(&evH, cudaEventDisableTiming);
        cudaEventCreateWithFlags(&evU, cudaEventDisableTiming);
        cudaFuncSetAttribute(gemm_big<0>, cudaFuncAttributeMaxDynamicSharedMemorySize, 92160);
        cudaFuncSetAttribute(gemm_big<1>, cudaFuncAttributeMaxDynamicSharedMemorySize, 92160);
        cudaFuncSetAttribute(attn_mma, cudaFuncAttributeMaxDynamicSharedMemorySize, 148224);
    }

    // s0 leads (capture-origin): input split   [R13 skeleton verbatim]
    split_in<<<(2 * L_SEQ * DM) / 256, 256>>>(x, sym);
    cudaEventRecord(ev0, 0);

    // s2: zero upper attn + small weights, then proj3 (needs split_in)
    zero_upper<<<dim3(L_SEQ, NH), 256, 0, s2>>>(attn);
    tsplit_small<<<dim3(32, 2, 3), 256, 0, s2>>>(wka, wkr, wv);
    cudaStreamWaitEvent(s2, ev0, 0);
    proj3<<<dim3(32, 3), 256, 0, s2>>>(fcos, fsin);
    cudaEventRecord(ev1, s2);

    // s0: big weights + fused q projections
    tsplit_big<<<dim3(32, 32, 3), 256>>>(wqa, wqr, wo);
    gemm_big<1><<<dim3(16, 16, 2), 256, 92160>>>(xh, xl, wqah, wqal, nullptr,
                                                 wqrh, wqrl, nullptr, fcos, fsin, 0);
    cudaStreamWaitEvent(0, ev1, 0);

    // attention heavy half (rows 1024..2047), then light half
    attn_mma<<<dim3(16, 16), 256, 148224>>>(attn, rel, 31);
    cudaEventRecord(evH, 0);
    attn_mma<<<dim3(16, 16), 256, 148224>>>(attn, rel, 15);

    // wo upper half overlapped with light attention (R9-proven fork pattern)
    cudaStreamWaitEvent(s2, evH, 0);
    gemm_big<0><<<dim3(16, 8, 1), 256, 92160, s2>>>(aoh, aol, woh, wol, out,
                                                    woh, wol, out, fcos, fsin, 1024);
    cudaEventRecord(evU, s2);

    // wo lower half after light attention
    gemm_big<0><<<dim3(16, 8, 1), 256, 92160>>>(aoh, aol, woh, wol, out,
                                                woh, wol, out, fcos, fsin, 0);
    cudaStreamWaitEvent(0, evU, 0);
}

// round 16
// speedup vs baseline: 1.0727x; 1.0727x over previous
#include <cuda_runtime.h>
#include <cuda_bf16.h>
#include <cstdint>
#include <cstddef>

#define L_SEQ 2048
#define DM    1024
#define NH    16
#define HD    64
#define RSCALE 0.125f
typedef __nv_bfloat16 bf16;
typedef __nv_bfloat162 bf162;
typedef unsigned int u32;

// ---------------- scratch ----------------
__device__ bf16 g_xh[L_SEQ*DM],  g_xl[L_SEQ*DM];
__device__ bf16 g_sh[L_SEQ*DM],  g_sl[L_SEQ*DM];
__device__ bf16 g_wqah[DM*DM], g_wqal[DM*DM];
__device__ bf16 g_wqrh[DM*DM], g_wqrl[DM*DM];
__device__ bf16 g_woh [DM*DM], g_wol [DM*DM];
__device__ bf16 g_wkah[HD*DM], g_wkal[HD*DM];
__device__ bf16 g_wkrh[HD*DM], g_wkrl[HD*DM];
__device__ bf16 g_wvh [HD*DM], g_wvl [HD*DM];
__device__ bf16 g_qah[NH*L_SEQ*HD], g_qal[NH*L_SEQ*HD];
__device__ bf16 g_qrh[NH*L_SEQ*HD], g_qrl[NH*L_SEQ*HD];
__device__ bf16 g_kah[L_SEQ*HD], g_kal[L_SEQ*HD];
__device__ bf16 g_krh[L_SEQ*HD], g_krl[L_SEQ*HD];
__device__ bf16 g_vth[HD*L_SEQ], g_vtl[HD*L_SEQ];
__device__ bf16 g_aoh[L_SEQ*DM], g_aol[L_SEQ*DM];

// ---------------- helpers ----------------
__device__ __forceinline__ void split2(float v, bf16& hi, bf16& lo) {
    hi = __float2bfloat16(v);
    lo = __float2bfloat16(v - __bfloat162float(hi));
}
__device__ __forceinline__ void packsplit(float a, float b, u32& ph, u32& pl) {
    float ah = __bfloat162float(__float2bfloat16(a));
    float bh = __bfloat162float(__float2bfloat16(b));
    bf162 hv = __floats2bfloat162_rn(ah, bh);
    bf162 lv = __floats2bfloat162_rn(a - ah, b - bh);
    ph = *reinterpret_cast<u32*>(&hv);
    pl = *reinterpret_cast<u32*>(&lv);
}
__device__ __forceinline__ void ldsm4(u32 addr, u32& r0, u32& r1, u32& r2, u32& r3) {
    asm volatile("ldmatrix.sync.aligned.m8n8.x4.shared.b16 {%0,%1,%2,%3}, [%4];"
                 : "=r"(r0), "=r"(r1), "=r"(r2), "=r"(r3) : "r"(addr));
}
__device__ __forceinline__ void hmma(float* c, u32 a0, u32 a1, u32 a2, u32 a3,
                                     u32 b0, u32 b1) {
    asm volatile("mma.sync.aligned.m16n8k16.row.col.f32.bf16.bf16.f32 "
                 "{%0,%1,%2,%3},{%4,%5,%6,%7},{%8,%9},{%0,%1,%2,%3};"
                 : "+f"(c[0]), "+f"(c[1]), "+f"(c[2]), "+f"(c[3])
                 : "r"(a0), "r"(a1), "r"(a2), "r"(a3), "r"(b0), "r"(b1));
}
__device__ __forceinline__ u32 addrA(u32 base, int ldb, int m0, int k0, int lane) {
    int g = lane & 7, grp = lane >> 3;
    return base + (u32)((m0 + g + (grp & 1) * 8) * ldb + (k0 + (grp >> 1) * 8) * 2);
}
__device__ __forceinline__ u32 addrB(u32 base, int ldb, int n0, int k0, int lane) {
    int g = lane & 7, grp = lane >> 3;
    return base + (u32)((n0 + g + (grp >> 1) * 8) * ldb + (k0 + (grp & 1) * 8) * 2);
}
__device__ __forceinline__ void cpasync16(u32 dst, const void* src) {
    asm volatile("cp.async.cg.shared.global [%0], [%1], 16;" :: "r"(dst), "l"(src));
}
__device__ __forceinline__ void cpcommit() { asm volatile("cp.async.commit_group;"); }
__device__ __forceinline__ void cpwait0() { asm volatile("cp.async.wait_group 0;"); }
__device__ __forceinline__ void cpwait1() { asm volatile("cp.async.wait_group 1;"); }
__device__ __forceinline__ void st_bf2(bf16* base, size_t off, float a, float b) {
    *reinterpret_cast<bf162*>(base + off) = __floats2bfloat162_rn(a, b);
}

// ---------------- input split ----------------
__global__ void split_in(const float* __restrict__ x, const float* __restrict__ s) {
    int i = blockIdx.x * 256 + threadIdx.x;
    if (i < L_SEQ * DM) {
        split2(x[i], g_xh[i], g_xl[i]);
    } else {
        int k = i - L_SEQ * DM;
        if (k < L_SEQ * DM) split2(s[k], g_sh[k], g_sl[k]);
    }
}

// ---------------- zero the non-causal attn region ----------------
__global__ __launch_bounds__(256) void zero_upper(float* __restrict__ attn) {
    const int i = blockIdx.x, hq = blockIdx.y;
    const int W = (((i >> 6) + 1) << 6);
    if (W >= L_SEQ) return;
    float* row = attn + ((size_t)hq * L_SEQ + i) * L_SEQ;
    float4 z = make_float4(0.f, 0.f, 0.f, 0.f);
    for (int c = W + threadIdx.x * 4; c < L_SEQ; c += 256 * 4)
        *(float4*)&row[c] = z;
}

// ---------------- weight transpose + split ----------------
__global__ void tsplit_big(const float* __restrict__ w0, const float* __restrict__ w1,
                           const float* __restrict__ w2) {
    __shared__ float t[32][33];
    int z = blockIdx.z;
    const float* src = (z == 0) ? w0 : (z == 1) ? w1 : w2;
    bf16* dh = (z == 0) ? g_wqah : (z == 1) ? g_wqrh : g_woh;
    bf16* dl = (z == 0) ? g_wqal : (z == 1) ? g_wqrl : g_wol;
    int k0 = blockIdx.x * 32, n0 = blockIdx.y * 32;
    int tx = threadIdx.x & 31, ty0 = threadIdx.x >> 5;
#pragma unroll
    for (int q = 0; q < 4; ++q) {
        int ty = ty0 * 4 + q;
        t[ty][tx] = src[(size_t)(k0 + ty) * DM + n0 + tx];
    }
    __syncthreads();
#pragma unroll
    for (int q = 0; q < 4; ++q) {
        int ty = ty0 * 4 + q;
        bf16 hh, ll; split2(t[tx][ty], hh, ll);
        size_t o = (size_t)(n0 + ty) * DM + k0 + tx;
        dh[o] = hh; dl[o] = ll;
    }
}
__global__ void tsplit_small(const float* __restrict__ w0, const float* __restrict__ w1,
                             const float* __restrict__ w2) {
    __shared__ float t[32][33];
    int z = blockIdx.z;
    const float* src = (z == 0) ? w0 : (z == 1) ? w1 : w2;
    bf16* dh = (z == 0) ? g_wkah : (z == 1) ? g_wkrh : g_wvh;
    bf16* dl = (z == 0) ? g_wkal : (z == 1) ? g_wkrl : g_wvl;
    int k0 = blockIdx.x * 32, n0 = blockIdx.y * 32;
    int tx = threadIdx.x & 31, ty0 = threadIdx.x >> 5;
#pragma unroll
    for (int q = 0; q < 4; ++q) {
        int ty = ty0 * 4 + q;
        t[ty][tx] = src[(size_t)(k0 + ty) * HD + n0 + tx];
    }
    __syncthreads();
#pragma unroll
    for (int q = 0; q < 4; ++q) {
        int ty = ty0 * 4 + q;
        bf16 hh, ll; split2(t[tx][ty], hh, ll);
        size_t o = (size_t)(n0 + ty) * DM + k0 + tx;
        dh[o] = hh; dl[o] = ll;
    }
}

// ---------------- big GEMM: BM=128 BN=64 BK=32, 3-stage, 2 CTA/SM ----------------
template <int MODE>
__global__ __launch_bounds__(256, 2) void gemm_big(
    const bf16* __restrict__ Ah,  const bf16* __restrict__ Al,
    const bf16* __restrict__ Bh0, const bf16* __restrict__ Bl0, float* __restrict__ C0,
    const bf16* __restrict__ Bh1, const bf16* __restrict__ Bl1, float* __restrict__ C1,
    const float* __restrict__ fcos, const float* __restrict__ fsin) {
    extern __shared__ bf16 dsm[];
    const bf16* Bh = blockIdx.z ? Bh1 : Bh0;
    const bf16* Bl = blockIdx.z ? Bl1 : Bl0;
    float* C = blockIdx.z ? C1 : C0;
    const int tid = threadIdx.x, lane = tid & 31, warp = tid >> 5;
    const int wm = warp & 3, wn = warp >> 2;
    const int m0 = blockIdx.y * 128, n0 = blockIdx.x * 64;
    u32 ub = (u32)__cvta_generic_to_shared(dsm);

    float acc[2][4][4];
#pragma unroll
    for (int m2 = 0; m2 < 2; ++m2)
#pragma unroll
        for (int o = 0; o < 4; ++o)
#pragma unroll
            for (int k = 0; k < 4; ++k) acc[m2][o][k] = 0.f;

    auto issue = [&](int k0, int st) {
        u32 base = ub + (u32)st * 30720u;
#pragma unroll
        for (int it = 0; it < 4; ++it) {
            int idx = it * 256 + tid;
            int pl = idx >> 9, rem = idx & 511, r = rem >> 2, s = rem & 3;
            const bf16* src = pl ? Al : Ah;
            cpasync16(base + (u32)pl * 10240u + r * 80 + s * 16,
                      src + (size_t)(m0 + r) * DM + k0 + s * 8);
        }
#pragma unroll
        for (int it = 0; it < 2; ++it) {
            int idx = it * 256 + tid;
            int pl = idx >> 8, rem = idx & 255, r = rem >> 2, s = rem & 3;
            const bf16* src = pl ? Bl : Bh;
            cpasync16(base + 20480u + (u32)pl * 5120u + r * 80 + s * 16,
                      src + (size_t)(n0 + r) * DM + k0 + s * 8);
        }
        cpcommit();
    };

    const int NK = DM / 32;
    issue(0, 0);
    issue(32, 1);
    for (int kt = 0; kt < NK; ++kt) {
        if (kt == NK - 1) cpwait0(); else cpwait1();
        __syncthreads();
        if (kt + 2 < NK) issue((kt + 2) * 32, (kt + 2) % 3);
        u32 base = ub + (u32)(kt % 3) * 30720u;
        u32 aH = base, aL = base + 10240u, bH = base + 20480u, bL = base + 25600u;
#pragma unroll
        for (int ks = 0; ks < 2; ++ks) {
            int kk = ks * 16;
            u32 ah[2][4], al[2][4], bh[2][4], bl[2][4];
#pragma unroll
            for (int m2 = 0; m2 < 2; ++m2) {
                ldsm4(addrA(aH, 80, wm * 32 + m2 * 16, kk, lane),
                      ah[m2][0], ah[m2][1], ah[m2][2], ah[m2][3]);
                ldsm4(addrA(aL, 80, wm * 32 + m2 * 16, kk, lane),
                      al[m2][0], al[m2][1], al[m2][2], al[m2][3]);
            }
#pragma unroll
            for (int q = 0; q < 2; ++q) {
                ldsm4(addrB(bH, 80, wn * 32 + q * 16, kk, lane),
                      bh[q][0], bh[q][1], bh[q][2], bh[q][3]);
                ldsm4(addrB(bL, 80, wn * 32 + q * 16, kk, lane),
                      bl[q][0], bl[q][1], bl[q][2], bl[q][3]);
            }
#pragma unroll
            for (int m2 = 0; m2 < 2; ++m2)
#pragma unroll
                for (int o = 0; o < 4; ++o) {
                    int q = o >> 1, pp = (o & 1) * 2;
                    hmma(acc[m2][o], ah[m2][0], ah[m2][1], ah[m2][2], ah[m2][3],
                         bh[q][pp], bh[q][pp + 1]);
                    hmma(acc[m2][o], ah[m2][0], ah[m2][1], ah[m2][2], ah[m2][3],
                         bl[q][pp], bl[q][pp + 1]);
                    hmma(acc[m2][o], al[m2][0], al[m2][1], al[m2][2], al[m2][3],
                         bh[q][pp], bh[q][pp + 1]);
                }
        }
    }
    const int g = lane >> 2, t = lane & 3;
    if (MODE == 0) {
#pragma unroll
        for (int m2 = 0; m2 < 2; ++m2)
#pragma unroll
            for (int o = 0; o < 4; ++o) {
                int row = m0 + wm * 32 + m2 * 16 + g;
                int col = n0 + wn * 32 + o * 8 + 2 * t;
                *(float2*)&C[(size_t)row * DM + col] = make_float2(acc[m2][o][0], acc[m2][o][1]);
                *(float2*)&C[(size_t)(row + 8) * DM + col] = make_float2(acc[m2][o][2], acc[m2][o][3]);
            }
    } else {
        bf16* dh = blockIdx.z ? g_qrh : g_qah;
        bf16* dl = blockIdx.z ? g_qrl : g_qal;
        const bool doRope = (blockIdx.z == 0);
#pragma unroll
        for (int m2 = 0; m2 < 2; ++m2)
#pragma unroll
            for (int o = 0; o < 4; ++o) {
                int col = n0 + wn * 32 + o * 8 + 2 * t;
                int hq = col >> 6, d = col & 63, pidx = d >> 1;
#pragma unroll
                for (int half = 0; half < 2; ++half) {
                    int row = m0 + wm * 32 + m2 * 16 + g + half * 8;
                    float v0 = acc[m2][o][half * 2], v1 = acc[m2][o][half * 2 + 1];
                    float o0, o1;
                    if (doRope) {
                        float cc = fcos[row * 32 + pidx], ss = fsin[row * 32 + pidx];
                        o0 = (v0 * cc - v1 * ss) * RSCALE;
                        o1 = (v0 * ss + v1 * cc) * RSCALE;
                    } else {
                        o0 = v0 * RSCALE; o1 = v1 * RSCALE;
                    }
                    bf16 h0, l0, h1, l1;
                    split2(o0, h0, l0); split2(o1, h1, l1);
                    size_t off = ((size_t)hq * L_SEQ + row) * HD + d;
                    st_bf2(dh, off, __bfloat162float(h0), __bfloat162float(h1));
                    st_bf2(dl, off, __bfloat162float(l0), __bfloat162float(l1));
                }
            }
    }
}

// ---------------- 3 small projections + rope/split/transpose epilogue ---------
__global__ __launch_bounds__(256, 2) void proj3(const float* __restrict__ fcos,
                                                const float* __restrict__ fsin) {
    __shared__ bf16 sA[2 * 2 * 64 * 40];
    __shared__ bf16 sB[2 * 2 * 64 * 40];
    const int z = blockIdx.y;
    const bf16* Ah = (z == 2) ? g_sh : g_xh;
    const bf16* Al = (z == 2) ? g_sl : g_xl;
    const bf16* Bh = (z == 0) ? g_wkah : (z == 1) ? g_wkrh : g_wvh;
    const bf16* Bl = (z == 0) ? g_wkal : (z == 1) ? g_wkrl : g_wvl;

    const int tid = threadIdx.x, lane = tid & 31, warp = tid >> 5;
    const int wm = warp & 3, wn = warp >> 2;
    const int m0 = blockIdx.x * 64;
    u32 ua = (u32)__cvta_generic_to_shared(sA);
    u32 ub = (u32)__cvta_generic_to_shared(sB);

    float acc[4][4];
#pragma unroll
    for (int o = 0; o < 4; ++o)
#pragma unroll
        for (int k = 0; k < 4; ++k) acc[o][k] = 0.f;

    auto issue = [&](int k0, int st) {
#pragma unroll
        for (int it = 0; it < 2; ++it) {
            int idx = it * 256 + tid;
            int pl = idx >> 8, rem = idx & 255, r = rem >> 2, s = rem & 3;
            const bf16* src = pl ? Al : Ah;
            cpasync16(ua + (u32)(st * 2 + pl) * 5120u + r * 80 + s * 16,
                      src + (size_t)(m0 + r) * DM + k0 + s * 8);
        }
#pragma unroll
        for (int it = 0; it < 2; ++it) {
            int idx = it * 256 + tid;
            int pl = idx >> 8, rem = idx & 255, r = rem >> 2, s = rem & 3;
            const bf16* src = pl ? Bl : Bh;
            cpasync16(ub + (u32)(st * 2 + pl) * 5120u + r * 80 + s * 16,
                      src + (size_t)r * DM + k0 + s * 8);
        }
        cpcommit();
    };

    issue(0, 0);
    const int NK = DM / 32;
    for (int kt = 0; kt < NK; ++kt) {
        if (kt + 1 < NK) { issue((kt + 1) * 32, (kt + 1) & 1); cpwait1(); }
        else cpwait0();
        __syncthreads();
        int st = kt & 1;
        u32 aH = ua + (u32)(st * 2) * 5120u, aL = aH + 5120u;
        u32 bH = ub + (u32)(st * 2) * 5120u, bL = bH + 5120u;
#pragma unroll
        for (int ks = 0; ks < 2; ++ks) {
            int kk = ks * 16;
            u32 ah[4], al[4], bh[2][4], bl[2][4];
            ldsm4(addrA(aH, 80, wm * 16, kk, lane), ah[0], ah[1], ah[2], ah[3]);
            ldsm4(addrA(aL, 80, wm * 16, kk, lane), al[0], al[1], al[2], al[3]);
#pragma unroll
            for (int q = 0; q < 2; ++q) {
                ldsm4(addrB(bH, 80, wn * 32 + q * 16, kk, lane),
                      bh[q][0], bh[q][1], bh[q][2], bh[q][3]);
                ldsm4(addrB(bL, 80, wn * 32 + q * 16, kk, lane),
                      bl[q][0], bl[q][1], bl[q][2], bl[q][3]);
            }
#pragma unroll
            for (int o = 0; o < 4; ++o) {
                int q = o >> 1, pp = (o & 1) * 2;
                hmma(acc[o], ah[0], ah[1], ah[2], ah[3], bh[q][pp], bh[q][pp + 1]);
                hmma(acc[o], ah[0], ah[1], ah[2], ah[3], bl[q][pp], bl[q][pp + 1]);
                hmma(acc[o], al[0], al[1], al[2], al[3], bh[q][pp], bh[q][pp + 1]);
            }
        }
        __syncthreads();
    }
    const int g = lane >> 2, t = lane & 3;
#pragma unroll
    for (int o = 0; o < 4; ++o) {
        int col = wn * 32 + o * 8 + 2 * t;
#pragma unroll
        for (int half = 0; half < 2; ++half) {
            int row = m0 + wm * 16 + g + half * 8;
            float v0 = acc[o][half * 2], v1 = acc[o][half * 2 + 1];
            if (z == 0) {
                int pidx = col >> 1;
                float cc = fcos[row * 32 + pidx], ss = fsin[row * 32 + pidx];
                float o0 = v0 * cc - v1 * ss, o1 = v0 * ss + v1 * cc;
                bf16 h0, l0, h1, l1;
                split2(o0, h0, l0); split2(o1, h1, l1);
                size_t off = (size_t)row * HD + col;
                st_bf2(g_kah, off, __bfloat162float(h0), __bfloat162float(h1));
                st_bf2(g_kal, off, __bfloat162float(l0), __bfloat162float(l1));
            } else if (z == 1) {
                bf16 h0, l0, h1, l1;
                split2(v0, h0, l0); split2(v1, h1, l1);
                size_t off = (size_t)row * HD + col;
                st_bf2(g_krh, off, __bfloat162float(h0), __bfloat162float(h1));
                st_bf2(g_krl, off, __bfloat162float(l0), __bfloat162float(l1));
            } else {
                bf16 h0, l0, h1, l1;
                split2(v0, h0, l0); split2(v1, h1, l1);
                g_vth[(size_t)col * L_SEQ + row] = h0;
                g_vtl[(size_t)col * L_SEQ + row] = l0;
                g_vth[(size_t)(col + 1) * L_SEQ + row] = h1;
                g_vtl[(size_t)(col + 1) * L_SEQ + row] = l1;
            }
        }
    }
}

// ---------------- attention: BM=64, 256 thr, 1D LPT grid (512 CTAs) ----------------
__device__ __forceinline__ void mma_qk16(u32 aH, u32 aL, u32 bH, u32 bL,
                                         int wm, int wn, int lane, float cs[4][4]) {
#pragma unroll
    for (int ks = 0; ks < 4; ++ks) {
        int k0 = ks * 16;
        u32 ah[4], al[4], bh[2][4], bl[2][4];
        ldsm4(addrA(aH, 144, wm * 16, k0, lane), ah[0], ah[1], ah[2], ah[3]);
        ldsm4(addrA(aL, 144, wm * 16, k0, lane), al[0], al[1], al[2], al[3]);
#pragma unroll
        for (int q = 0; q < 2; ++q) {
            ldsm4(addrB(bH, 144, wn * 32 + q * 16, k0, lane),
                  bh[q][0], bh[q][1], bh[q][2], bh[q][3]);
            ldsm4(addrB(bL, 144, wn * 32 + q * 16, k0, lane),
                  bl[q][0], bl[q][1], bl[q][2], bl[q][3]);
        }
#pragma unroll
        for (int o = 0; o < 4; ++o) {
            int q = o >> 1, pp = (o & 1) * 2;
            hmma(cs[o], ah[0], ah[1], ah[2], ah[3], bh[q][pp], bh[q][pp + 1]);
            hmma(cs[o], ah[0], ah[1], ah[2], ah[3], bl[q][pp], bl[q][pp + 1]);
            hmma(cs[o], al[0], al[1], al[2], al[3], bh[q][pp], bh[q][pp + 1]);
        }
    }
}

__device__ __forceinline__ void store_frag16(float* dst, float c[4][4],
                                             int wm, int wn, int g, int t) {
#pragma unroll
    for (int o = 0; o < 4; ++o) {
        int row = wm * 16 + g;
        int col = wn * 32 + o * 8 + 2 * t;
        *(float2*)&dst[(size_t)row * L_SEQ + col] = make_float2(c[o][0], c[o][1]);
        *(float2*)&dst[(size_t)(row + 8) * L_SEQ + col] = make_float2(c[o][2], c[o][3]);
    }
}

#define ASM_RING 36864u
#define ASM_LS   147456u

__global__ __launch_bounds__(256, 1) void attn_mma(float* __restrict__ attn_out,
                                                   float* __restrict__ rel_out) {
    extern __shared__ char smraw[];
    u32 usm = (u32)__cvta_generic_to_shared(smraw);
    float* lsum = (float*)(smraw + ASM_LS);
    float* linv = lsum + 128;
    float* osc  = (float*)(smraw + ASM_RING);

    // LPT: all ib=31 tiles (heaviest) first across heads, then ib=30, ...
    const int b = blockIdx.x;
    const int ib = 31 - (b >> 4);
    const int hq = b & 15;
    const int i0 = ib * 64;
    const int tid = threadIdx.x, lane = tid & 31, warp = tid >> 5;
    const int wm = warp >> 1, wn = warp & 1;
    const int g = lane >> 2, t = lane & 3;
    const int jtmax = ib;

    {
        const bf16* srcs[4] = {g_qah + ((size_t)hq * L_SEQ + i0) * HD,
                               g_qal + ((size_t)hq * L_SEQ + i0) * HD,
                               g_qrh + ((size_t)hq * L_SEQ + i0) * HD,
                               g_qrl + ((size_t)hq * L_SEQ + i0) * HD};
#pragma unroll
        for (int a = 0; a < 4; ++a)
#pragma unroll
            for (int it = 0; it < 2; ++it) {
                int idx = it * 256 + tid;
                int r = idx >> 3, s = idx & 7;
                *(uint4*)(smraw + a * 9216 + r * 144 + s * 16) =
                    *(const uint4*)&srcs[a][(size_t)r * HD + s * 8];
            }
    }
    const u32 uqa_h = usm, uqa_l = usm + 9216u;
    const u32 uqr_h = usm + 18432u, uqr_l = usm + 27648u;
    auto ring = [&](int st, int pl) -> u32 {
        return usm + ASM_RING + (u32)st * 55296u + (u32)pl * 9216u;
    };

    auto issue_tiles = [&](int jt, int st, bool causal) {
#pragma unroll
        for (int it = 0; it < 4; ++it) {
            int idx = it * 256 + tid;
            int pl = idx >> 9, rem = idx & 511, r = rem >> 3, s = rem & 7;
            const bf16* src = pl ? g_krl : g_krh;
            cpasync16(ring(st, 2 + pl) + r * 144 + s * 16,
                      src + (size_t)(jt * 64 + r) * HD + s * 8);
        }
        if (causal) {
#pragma unroll
            for (int it = 0; it < 4; ++it) {
                int idx = it * 256 + tid;
                int pl = idx >> 9, rem = idx & 511, r = rem >> 3, s = rem & 7;
                const bf16* src = pl ? g_kal : g_kah;
                cpasync16(ring(st, pl) + r * 144 + s * 16,
                          src + (size_t)(jt * 64 + r) * HD + s * 8);
            }
#pragma unroll
            for (int it = 0; it < 4; ++it) {
                int idx = it * 256 + tid;
                int pl = idx >> 9, rem = idx & 511, r = rem >> 3, s = rem & 7;
                const bf16* src = pl ? g_vtl : g_vth;
                cpasync16(ring(st, 4 + pl) + r * 144 + s * 16,
                          src + (size_t)r * L_SEQ + jt * 64 + s * 8);
            }
        }
        cpcommit();
    };

    float esum[2] = {0.f, 0.f};
    float co[8][4];
#pragma unroll
    for (int o = 0; o < 8; ++o)
#pragma unroll
        for (int k = 0; k < 4; ++k) co[o][k] = 0.f;

    float* attnp = attn_out + (size_t)hq * L_SEQ * L_SEQ + (size_t)i0 * L_SEQ;
    float* relp  = rel_out  + (size_t)hq * L_SEQ * L_SEQ + (size_t)i0 * L_SEQ;

    issue_tiles(0, 0, true);
    for (int jt = 0; jt < 32; ++jt) {
        const bool causal = (jt <= jtmax);
        cpwait0();
        __syncthreads();
        if (jt < 31) issue_tiles(jt + 1, (jt + 1) & 1, (jt + 1) <= jtmax);
        int st = jt & 1;

        float cr[4][4];
#pragma unroll
        for (int o = 0; o < 4; ++o)
#pragma unroll
            for (int k = 0; k < 4; ++k) cr[o][k] = 0.f;
        mma_qk16(uqr_h, uqr_l, ring(st, 2), ring(st, 3), wm, wn, lane, cr);
        store_frag16(relp + jt * 64, cr, wm, wn, g, t);

        if (!causal) continue;

        float csq[4][4];
#pragma unroll
        for (int o = 0; o < 4; ++o)
#pragma unroll
            for (int k = 0; k < 4; ++k) csq[o][k] = 0.f;
        mma_qk16(uqa_h, uqa_l, ring(st, 0), ring(st, 1), wm, wn, lane, csq);

        const bool dia = (jt == ib);
        const int r0 = i0 + wm * 16 + g;
#pragma unroll
        for (int o = 0; o < 4; ++o) {
            int cb = jt * 64 + wn * 32 + o * 8 + 2 * t;
            float p0 = __expf(csq[o][0]);
            float p1 = __expf(csq[o][1]);
            float p2 = __expf(csq[o][2]);
            float p3 = __expf(csq[o][3]);
            if (dia) {
                if (cb     > r0)     p0 = 0.f;
                if (cb + 1 > r0)     p1 = 0.f;
                if (cb     > r0 + 8) p2 = 0.f;
                if (cb + 1 > r0 + 8) p3 = 0.f;
            }
            esum[0] += p0 + p1;
            esum[1] += p2 + p3;
            csq[o][0] = p0; csq[o][1] = p1; csq[o][2] = p2; csq[o][3] = p3;
        }
        store_frag16(attnp + jt * 64, csq, wm, wn, g, t);

#pragma unroll
        for (int bb = 0; bb < 2; ++bb) {
            float pr[8];
#pragma unroll
            for (int k = 0; k < 4; ++k) {
                pr[k]     = csq[2 * bb][k]     * cr[2 * bb][k];
                pr[4 + k] = csq[2 * bb + 1][k] * cr[2 * bb + 1][k];
            }
            u32 aH[4], aL[4];
            packsplit(pr[0], pr[1], aH[0], aL[0]);
            packsplit(pr[2], pr[3], aH[1], aL[1]);
            packsplit(pr[4], pr[5], aH[2], aL[2]);
            packsplit(pr[6], pr[7], aH[3], aL[3]);
#pragma unroll
            for (int q2 = 0; q2 < 4; ++q2) {
                u32 vh[4], vl[4];
                ldsm4(addrB(ring(st, 4), 144, q2 * 16, wn * 32 + bb * 16, lane),
                      vh[0], vh[1], vh[2], vh[3]);
                ldsm4(addrB(ring(st, 5), 144, q2 * 16, wn * 32 + bb * 16, lane),
                      vl[0], vl[1], vl[2], vl[3]);
#pragma unroll
                for (int sub = 0; sub < 2; ++sub) {
                    int o = q2 * 2 + sub, pp = sub * 2;
                    hmma(co[o], aH[0], aH[1], aH[2], aH[3], vh[pp], vh[pp + 1]);
                    hmma(co[o], aH[0], aH[1], aH[2], aH[3], vl[pp], vl[pp + 1]);
                    hmma(co[o], aL[0], aL[1], aL[2], aL[3], vh[pp], vh[pp + 1]);
                }
            }
        }
    }

#pragma unroll
    for (int hf = 0; hf < 2; ++hf) {
        float v = esum[hf];
        v += __shfl_xor_sync(0xffffffffu, v, 1);
        v += __shfl_xor_sync(0xffffffffu, v, 2);
        esum[hf] = v;
    }
    __syncthreads();
    if (t == 0) {
        lsum[wn * 64 + wm * 16 + g] = esum[0];
        lsum[wn * 64 + wm * 16 + g + 8] = esum[1];
    }
    __syncthreads();
    if (tid < 64) linv[tid] = __fdividef(1.f, lsum[tid] + lsum[64 + tid]);
    __syncthreads();

    if (wn == 0) {
#pragma unroll
        for (int o = 0; o < 8; ++o) {
            int row = wm * 16 + g;
            int col = o * 8 + 2 * t;
            *(float2*)&osc[row * 68 + col] = make_float2(co[o][0], co[o][1]);
            *(float2*)&osc[(row + 8) * 68 + col] = make_float2(co[o][2], co[o][3]);
        }
    }
    __syncthreads();
    if (wn == 1) {
#pragma unroll
        for (int o = 0; o < 8; ++o) {
            int row = wm * 16 + g;
            int col = o * 8 + 2 * t;
            osc[row * 68 + col]           += co[o][0];
            osc[row * 68 + col + 1]       += co[o][1];
            osc[(row + 8) * 68 + col]     += co[o][2];
            osc[(row + 8) * 68 + col + 1] += co[o][3];
        }
    }
    __syncthreads();
#pragma unroll
    for (int it = 0; it < 16; ++it) {
        int idx = it * 256 + tid;
        int r = idx >> 6, d = idx & 63;
        float v = osc[r * 68 + d] * linv[r];
        bf16 hh, ll; split2(v, hh, ll);
        size_t off = (size_t)(i0 + r) * DM + hq * 64 + d;
        g_aoh[off] = hh; g_aol[off] = ll;
    }

    {
        int r = tid >> 2;
        float sc = linv[r];
        int Wr = (ib + 1) << 6;
        float* row = attnp + (size_t)r * L_SEQ;
        for (int c = (tid & 3) * 4; c < Wr; c += 16) {
            float4 v = *(float4*)&row[c];
            v.x *= sc; v.y *= sc; v.z *= sc; v.w *= sc;
            *(float4*)&row[c] = v;
        }
    }
}

// ---------------------------------- launch ----------------------------------
extern "C" void kernel_launch(void* const* d_in, const int* in_sizes, int n_in,
                              void* d_out, int out_size) {
    (void)in_sizes; (void)n_in; (void)out_size;
    const float* x    = (const float*)d_in[0];
    const float* sym  = (const float*)d_in[1];
    const float* fcos = (const float*)d_in[2];
    const float* fsin = (const float*)d_in[3];
    const float* wqa  = (const float*)d_in[4];
    const float* wka  = (const float*)d_in[5];
    const float* wqr  = (const float*)d_in[6];
    const float* wkr  = (const float*)d_in[7];
    const float* wv   = (const float*)d_in[8];
    const float* wo   = (const float*)d_in[9];

    float* out  = (float*)d_out;
    float* attn = out + (size_t)L_SEQ * DM;
    float* rel  = attn + (size_t)NH * L_SEQ * L_SEQ;

    void* p;
#define GS(var, sym_) cudaGetSymbolAddress(&p, sym_); bf16* var = (bf16*)p;
    GS(xh, g_xh)   GS(xl, g_xl)
    GS(wqah, g_wqah) GS(wqal, g_wqal) GS(wqrh, g_wqrh) GS(wqrl, g_wqrl)
    GS(woh, g_woh)   GS(wol, g_wol)
    GS(aoh, g_aoh)   GS(aol, g_aol)
#undef GS

    static cudaStream_t s2 = nullptr;
    static cudaEvent_t ev0 = nullptr, ev1 = nullptr;
    if (!s2) {
        cudaStreamCreateWithFlags(&s2, cudaStreamNonBlocking);
        cudaEventCreateWithFlags(&ev0, cudaEventDisableTiming);
        cudaEventCreateWithFlags(&ev1, cudaEventDisableTiming);
        cudaFuncSetAttribute(gemm_big<0>, cudaFuncAttributeMaxDynamicSharedMemorySize, 92160);
        cudaFuncSetAttribute(gemm_big<1>, cudaFuncAttributeMaxDynamicSharedMemorySize, 92160);
        cudaFuncSetAttribute(attn_mma, cudaFuncAttributeMaxDynamicSharedMemorySize, 148224);
    }

    // s0 leads (capture-origin): input split   [R13 skeleton verbatim]
    split_in<<<(2 * L_SEQ * DM) / 256, 256>>>(x, sym);
    cudaEventRecord(ev0, 0);

    // s2: zero upper attn + small weights, then proj3 (needs split_in)
    zero_upper<<<dim3(L_SEQ, NH), 256, 0, s2>>>(attn);
    tsplit_small<<<dim3(32, 2, 3), 256, 0, s2>>>(wka, wkr, wv);
    cudaStreamWaitEvent(s2, ev0, 0);
    proj3<<<dim3(32, 3), 256, 0, s2>>>(fcos, fsin);
    cudaEventRecord(ev1, s2);

    // s0: big weights + fused q projections
    tsplit_big<<<dim3(32, 32, 3), 256>>>(wqa, wqr, wo);
    gemm_big<1><<<dim3(16, 16, 2), 256, 92160>>>(xh, xl, wqah, wqal, nullptr,
                                                 wqrh, wqrl, nullptr, fcos, fsin);
    cudaStreamWaitEvent(0, ev1, 0);

    // attention: single launch, global LPT ordering
    attn_mma<<<dim3(512), 256, 148224>>>(attn, rel);

    // output projection
    gemm_big<0><<<dim3(16, 16, 1), 256, 92160>>>(aoh, aol, woh, wol, out,
                                                 woh, wol, out, fcos, fsin);
}